// round 1
// baseline (speedup 1.0000x reference)
#include <cuda_runtime.h>
#include <math.h>

#define Bdim 4
#define Sdim 2048
#define Ddim 1024
#define Hdim 16
#define HDdim 64
#define Fdim 4096
#define Mdim (Bdim * Sdim)   // 8192
#define EPS 1e-5f

// ---------------------------------------------------------------------------
// Scratch: 11 * M * D floats = 369 MB static device memory (allowed workaround
// for the no-alloc rule).
//   [0]  xn1      (M*D)
//   [1]  q        (M*D)  layout [B,H,S,HD]
//   [2]  k        (M*D)
//   [3]  v        (M*D)
//   [4]  attnout  (M*D)  layout [B,S,D]
//   [5]  x1       (M*D)
//   [6]  xn2      (M*D)
//   [7..10] h     (M*F = 4*M*D)
// ---------------------------------------------------------------------------
#define MD ((size_t)Mdim * Ddim)
__device__ float g_scratch[11 * MD];

// ===========================================================================
// LayerNorm: one block (256 threads) per row of 1024 floats.
// ===========================================================================
__global__ __launch_bounds__(256) void ln_kernel(const float* __restrict__ X,
                                                 const float* __restrict__ G,
                                                 const float* __restrict__ Bt,
                                                 float* __restrict__ Y) {
    int row = blockIdx.x;
    int t = threadIdx.x;
    const float4* xr = (const float4*)(X + (size_t)row * Ddim);
    float4 v = xr[t];
    float s  = v.x + v.y + v.z + v.w;
    float ss = v.x * v.x + v.y * v.y + v.z * v.z + v.w * v.w;

    // warp reduce
    #pragma unroll
    for (int off = 16; off > 0; off >>= 1) {
        s  += __shfl_xor_sync(0xffffffffu, s,  off);
        ss += __shfl_xor_sync(0xffffffffu, ss, off);
    }
    __shared__ float red_s[8], red_q[8];
    int wid = t >> 5, lane = t & 31;
    if (lane == 0) { red_s[wid] = s; red_q[wid] = ss; }
    __syncthreads();
    float S_ = 0.f, Q_ = 0.f;
    #pragma unroll
    for (int i = 0; i < 8; i++) { S_ += red_s[i]; Q_ += red_q[i]; }

    float mu   = S_ * (1.0f / Ddim);
    float var  = Q_ * (1.0f / Ddim) - mu * mu;
    float rstd = rsqrtf(var + EPS);

    float4 g4 = ((const float4*)G)[t];
    float4 b4 = ((const float4*)Bt)[t];
    float4 y;
    y.x = (v.x - mu) * rstd * g4.x + b4.x;
    y.y = (v.y - mu) * rstd * g4.y + b4.y;
    y.z = (v.z - mu) * rstd * g4.z + b4.z;
    y.w = (v.w - mu) * rstd * g4.w + b4.w;
    ((float4*)(Y + (size_t)row * Ddim))[t] = y;
}

// ===========================================================================
// SGEMM: C[M,N] = A[M,K] @ W[K,N] + bias, with epilogue modes.
// BM=BN=128, BK=8, 256 threads, 8x8 microtile, double-buffered smem.
// ===========================================================================
#define MODE_PLAIN 0
#define MODE_RES   1
#define MODE_GELU  2
#define MODE_QKV   3

template <int MODE>
__global__ __launch_bounds__(256) void sgemm_kernel(
    const float* __restrict__ A, const float* __restrict__ W,
    const float* __restrict__ bias, const float* __restrict__ Res,
    float* __restrict__ C, int Mn, int Nn, int Kn) {
    __shared__ float As[2][8][128];
    __shared__ float Bs[2][8][128];

    int t  = threadIdx.x;
    int bm = blockIdx.y * 128;
    int bn = blockIdx.x * 128;

    int ar = t >> 1;            // 0..127  A row within tile
    int ak = (t & 1) * 4;       // 0 or 4  A k offset
    int bkr = t >> 5;           // 0..7    B k row
    int bc  = (t & 31) * 4;     // 0..124  B col offset
    int tx = t & 15, ty = t >> 4;

    const float* Ap = A + (size_t)(bm + ar) * Kn + ak;
    const float* Bp = W + (size_t)bkr * Nn + bn + bc;

    // preload tile 0
    float4 pa = *(const float4*)Ap;
    float4 pb = *(const float4*)Bp;
    As[0][ak + 0][ar] = pa.x;
    As[0][ak + 1][ar] = pa.y;
    As[0][ak + 2][ar] = pa.z;
    As[0][ak + 3][ar] = pa.w;
    *(float4*)&Bs[0][bkr][bc] = pb;
    __syncthreads();

    float c[8][8];
    #pragma unroll
    for (int i = 0; i < 8; i++)
        #pragma unroll
        for (int j = 0; j < 8; j++) c[i][j] = 0.f;

    int ntiles = Kn >> 3;
    int sbuf = 0;
    for (int tile = 0; tile < ntiles; tile++) {
        if (tile + 1 < ntiles) {
            pa = *(const float4*)(Ap + (tile + 1) * 8);
            pb = *(const float4*)(Bp + (size_t)(tile + 1) * 8 * Nn);
        }
        #pragma unroll
        for (int kk = 0; kk < 8; kk++) {
            float4 a0 = *(float4*)&As[sbuf][kk][ty * 8];
            float4 a1 = *(float4*)&As[sbuf][kk][ty * 8 + 4];
            float4 b0 = *(float4*)&Bs[sbuf][kk][tx * 8];
            float4 b1 = *(float4*)&Bs[sbuf][kk][tx * 8 + 4];
            float av[8] = {a0.x, a0.y, a0.z, a0.w, a1.x, a1.y, a1.z, a1.w};
            float bv[8] = {b0.x, b0.y, b0.z, b0.w, b1.x, b1.y, b1.z, b1.w};
            #pragma unroll
            for (int i = 0; i < 8; i++)
                #pragma unroll
                for (int j = 0; j < 8; j++) c[i][j] += av[i] * bv[j];
        }
        if (tile + 1 < ntiles) {
            As[sbuf ^ 1][ak + 0][ar] = pa.x;
            As[sbuf ^ 1][ak + 1][ar] = pa.y;
            As[sbuf ^ 1][ak + 2][ar] = pa.z;
            As[sbuf ^ 1][ak + 3][ar] = pa.w;
            *(float4*)&Bs[sbuf ^ 1][bkr][bc] = pb;
        }
        __syncthreads();
        sbuf ^= 1;
    }

    // epilogue
    #pragma unroll
    for (int i = 0; i < 8; i++) {
        int m = bm + ty * 8 + i;
        #pragma unroll
        for (int j4 = 0; j4 < 8; j4 += 4) {
            int n = bn + tx * 8 + j4;
            float4 vv;
            float4 bb = *(const float4*)(bias + n);
            vv.x = c[i][j4 + 0] + bb.x;
            vv.y = c[i][j4 + 1] + bb.y;
            vv.z = c[i][j4 + 2] + bb.z;
            vv.w = c[i][j4 + 3] + bb.w;
            if (MODE == MODE_RES) {
                float4 rr = *(const float4*)(Res + (size_t)m * Nn + n);
                vv.x += rr.x; vv.y += rr.y; vv.z += rr.z; vv.w += rr.w;
            }
            if (MODE == MODE_GELU) {
                vv.x = 0.5f * vv.x * (1.f + erff(vv.x * 0.70710678118654752f));
                vv.y = 0.5f * vv.y * (1.f + erff(vv.y * 0.70710678118654752f));
                vv.z = 0.5f * vv.z * (1.f + erff(vv.z * 0.70710678118654752f));
                vv.w = 0.5f * vv.w * (1.f + erff(vv.w * 0.70710678118654752f));
            }
            if (MODE == MODE_QKV) {
                // [B,S,D] row m, col n  ->  [B,H,S,HD]
                int b_ = m >> 11;          // m / S
                int s_ = m & 2047;         // m % S
                int h_ = n >> 6;           // n / HD
                int hd = n & 63;           // n % HD
                size_t o = ((((size_t)b_ * Hdim + h_) * Sdim + s_) * HDdim) + hd;
                *(float4*)(C + o) = vv;
            } else {
                *(float4*)(C + (size_t)m * Nn + n) = vv;
            }
        }
    }
}

// ===========================================================================
// Flash-style attention.  Grid: (S/64, B*H), 256 threads.
// Q,K,V in [B,H,S,HD]; output written in [B,S,D].
// smem: q_sm[d][q], k_sm[d][j], v_sm[j][d], p_sm[j][q]; rows padded to 68.
// ===========================================================================
#define PAD 68
#define ATTN_SMEM (4 * 64 * PAD * 4)

__global__ __launch_bounds__(256) void attention_kernel(
    const float* __restrict__ Q, const float* __restrict__ K,
    const float* __restrict__ V, float* __restrict__ O) {
    extern __shared__ float sm[];
    float* q_sm = sm;                    // [64][PAD]  (d-major)
    float* k_sm = sm + 64 * PAD;         // [64][PAD]  (d-major)
    float* v_sm = sm + 2 * 64 * PAD;     // [64][PAD]  (j-major)
    float* p_sm = sm + 3 * 64 * PAD;     // [64][PAD]  (k-major)

    int t  = threadIdx.x;
    int bh = blockIdx.y;                 // b*H + h
    int q0 = blockIdx.x * 64;
    int b_ = bh / Hdim, h_ = bh % Hdim;

    const float* Qb = Q + ((size_t)bh * Sdim + q0) * HDdim;
    const float* Kb = K + (size_t)bh * Sdim * HDdim;
    const float* Vb = V + (size_t)bh * Sdim * HDdim;

    int tq = t >> 4;   // 0..15 : query group (4 queries)
    int tk = t & 15;   // 0..15 : key/dim group (4 cols)

    // load Q tile transposed, pre-scaled by 1/sqrt(HD)
    #pragma unroll
    for (int r = 0; r < 4; r++) {
        int f = t + r * 256;             // float4 index, 0..1023
        int row = f >> 4;                // query 0..63
        int dc = (f & 15) << 2;          // dim 0..60
        float4 qv = *(const float4*)(Qb + row * HDdim + dc);
        q_sm[(dc + 0) * PAD + row] = qv.x * 0.125f;
        q_sm[(dc + 1) * PAD + row] = qv.y * 0.125f;
        q_sm[(dc + 2) * PAD + row] = qv.z * 0.125f;
        q_sm[(dc + 3) * PAD + row] = qv.w * 0.125f;
    }

    float o_acc[4][4];
    #pragma unroll
    for (int i = 0; i < 4; i++)
        #pragma unroll
        for (int j = 0; j < 4; j++) o_acc[i][j] = 0.f;
    float m_run[4] = {-1e30f, -1e30f, -1e30f, -1e30f};
    float l_run[4] = {0.f, 0.f, 0.f, 0.f};

    for (int kt = 0; kt < Sdim / 64; kt++) {
        __syncthreads();   // protect k_sm/v_sm/p_sm reuse from previous iter
        const float* Kt = Kb + (size_t)kt * 64 * HDdim;
        const float* Vt = Vb + (size_t)kt * 64 * HDdim;
        #pragma unroll
        for (int r = 0; r < 4; r++) {
            int f = t + r * 256;
            int row = f >> 4;
            int dc = (f & 15) << 2;
            float4 kv = *(const float4*)(Kt + row * HDdim + dc);
            k_sm[(dc + 0) * PAD + row] = kv.x;
            k_sm[(dc + 1) * PAD + row] = kv.y;
            k_sm[(dc + 2) * PAD + row] = kv.z;
            k_sm[(dc + 3) * PAD + row] = kv.w;
            float4 vv = *(const float4*)(Vt + row * HDdim + dc);
            *(float4*)&v_sm[row * PAD + dc] = vv;
        }
        __syncthreads();

        // scores: s[4q][4k]
        float s4[4][4];
        #pragma unroll
        for (int i = 0; i < 4; i++)
            #pragma unroll
            for (int j = 0; j < 4; j++) s4[i][j] = 0.f;
        #pragma unroll 8
        for (int d = 0; d < 64; d++) {
            float4 aq = *(float4*)&q_sm[d * PAD + tq * 4];
            float4 bk = *(float4*)&k_sm[d * PAD + tk * 4];
            float av[4] = {aq.x, aq.y, aq.z, aq.w};
            float bv[4] = {bk.x, bk.y, bk.z, bk.w};
            #pragma unroll
            for (int i = 0; i < 4; i++)
                #pragma unroll
                for (int j = 0; j < 4; j++) s4[i][j] += av[i] * bv[j];
        }

        // online softmax per query row (row group = 16 lanes sharing tq)
        #pragma unroll
        for (int qi = 0; qi < 4; qi++) {
            float tmax = fmaxf(fmaxf(s4[qi][0], s4[qi][1]),
                               fmaxf(s4[qi][2], s4[qi][3]));
            #pragma unroll
            for (int off = 8; off > 0; off >>= 1)
                tmax = fmaxf(tmax, __shfl_xor_sync(0xffffffffu, tmax, off));
            float m_new = fmaxf(m_run[qi], tmax);
            float alpha = __expf(m_run[qi] - m_new);
            m_run[qi] = m_new;
            float psum = 0.f;
            #pragma unroll
            for (int j = 0; j < 4; j++) {
                s4[qi][j] = __expf(s4[qi][j] - m_new);
                psum += s4[qi][j];
            }
            #pragma unroll
            for (int off = 8; off > 0; off >>= 1)
                psum += __shfl_xor_sync(0xffffffffu, psum, off);
            l_run[qi] = l_run[qi] * alpha + psum;
            #pragma unroll
            for (int j = 0; j < 4; j++) o_acc[qi][j] *= alpha;
            // write p transposed: p_sm[key][query]
            #pragma unroll
            for (int j = 0; j < 4; j++)
                p_sm[(tk * 4 + j) * PAD + tq * 4 + qi] = s4[qi][j];
        }
        __syncthreads();

        // o += p @ V : tk now serves as dim group
        #pragma unroll 8
        for (int kk = 0; kk < 64; kk++) {
            float4 pp = *(float4*)&p_sm[kk * PAD + tq * 4];
            float4 vv = *(float4*)&v_sm[kk * PAD + tk * 4];
            float pv[4] = {pp.x, pp.y, pp.z, pp.w};
            float vvv[4] = {vv.x, vv.y, vv.z, vv.w};
            #pragma unroll
            for (int i = 0; i < 4; i++)
                #pragma unroll
                for (int j = 0; j < 4; j++) o_acc[i][j] += pv[i] * vvv[j];
        }
    }

    // write output in [B,S,D]
    #pragma unroll
    for (int qi = 0; qi < 4; qi++) {
        float inv = 1.0f / l_run[qi];
        int qrow = q0 + tq * 4 + qi;
        float4 r;
        r.x = o_acc[qi][0] * inv;
        r.y = o_acc[qi][1] * inv;
        r.z = o_acc[qi][2] * inv;
        r.w = o_acc[qi][3] * inv;
        size_t off = ((size_t)b_ * Sdim + qrow) * Ddim + h_ * HDdim + tk * 4;
        *(float4*)(O + off) = r;
    }
}

// ===========================================================================
// Launch
// ===========================================================================
extern "C" void kernel_launch(void* const* d_in, const int* in_sizes, int n_in,
                              void* d_out, int out_size) {
    const float* x   = (const float*)d_in[0];
    const float* Wq  = (const float*)d_in[1];
    const float* bq  = (const float*)d_in[2];
    const float* Wk  = (const float*)d_in[3];
    const float* bk  = (const float*)d_in[4];
    const float* Wv  = (const float*)d_in[5];
    const float* bv  = (const float*)d_in[6];
    const float* Wo  = (const float*)d_in[7];
    const float* bo  = (const float*)d_in[8];
    const float* W1  = (const float*)d_in[9];
    const float* b1  = (const float*)d_in[10];
    const float* W2  = (const float*)d_in[11];
    const float* b2  = (const float*)d_in[12];
    const float* g1  = (const float*)d_in[13];
    const float* be1 = (const float*)d_in[14];
    const float* g2  = (const float*)d_in[15];
    const float* be2 = (const float*)d_in[16];
    float* out = (float*)d_out;

    float* base = nullptr;
    cudaGetSymbolAddress((void**)&base, g_scratch);
    float* xn  = base;
    float* q   = base + 1 * MD;
    float* k   = base + 2 * MD;
    float* v   = base + 3 * MD;
    float* att = base + 4 * MD;
    float* x1  = base + 5 * MD;
    float* xn2 = base + 6 * MD;
    float* h   = base + 7 * MD;

    cudaFuncSetAttribute(attention_kernel,
                         cudaFuncAttributeMaxDynamicSharedMemorySize,
                         ATTN_SMEM);

    dim3 blk(256);
    dim3 gD(Ddim / 128, Mdim / 128);   // N=1024 GEMMs
    dim3 gF(Fdim / 128, Mdim / 128);   // N=4096 GEMM

    ln_kernel<<<Mdim, blk>>>(x, g1, be1, xn);
    sgemm_kernel<MODE_QKV><<<gD, blk>>>(xn, Wq, bq, nullptr, q, Mdim, Ddim, Ddim);
    sgemm_kernel<MODE_QKV><<<gD, blk>>>(xn, Wk, bk, nullptr, k, Mdim, Ddim, Ddim);
    sgemm_kernel<MODE_QKV><<<gD, blk>>>(xn, Wv, bv, nullptr, v, Mdim, Ddim, Ddim);
    attention_kernel<<<dim3(Sdim / 64, Bdim * Hdim), blk, ATTN_SMEM>>>(q, k, v, att);
    sgemm_kernel<MODE_RES><<<gD, blk>>>(att, Wo, bo, x, x1, Mdim, Ddim, Ddim);
    ln_kernel<<<Mdim, blk>>>(x1, g2, be2, xn2);
    sgemm_kernel<MODE_GELU><<<gF, blk>>>(xn2, W1, b1, nullptr, h, Mdim, Fdim, Ddim);
    sgemm_kernel<MODE_RES><<<gD, blk>>>(h, W2, b2, x1, out, Mdim, Ddim, Fdim);
}